// round 2
// baseline (speedup 1.0000x reference)
#include <cuda_runtime.h>
#include <cuda_bf16.h>
#include <cstdint>
#include <math.h>

#define NSTEPS 100
#define NU     128
#define BTOT   200000
#define TILE_M 128
#define NTHREADS 128

// ---------------- SMEM layout (dynamic) ----------------
// H ping/pong: 128 rows x 128 bf16 cols = 256B/row, XOR-swizzled in 16B chunks.
#define SM_HP   0
#define SM_HQ   32768
#define SM_F32  65536

// float region indices (within fA)
#define F_W0A   0
#define F_W0B   128
#define F_W3A   256      // (unused by MMA path, kept for layout stability)
#define F_W3B   384
#define F_BE0   512
#define F_BE1   640
#define F_BE2   768
#define F_COEF  896
#define F_INVAS 1024
#define F_BSQ   1152
#define F_B3    1280
#define F_PRED  1312     // 256 floats: per-row (p0,p1)
#define F_TOTAL (F_PRED + 256)
#define SMEM_TOTAL (SM_F32 + F_TOTAL * 4)

// ---------------- helpers ----------------
static __device__ __forceinline__ uint32_t smem_u32(const void* p) {
    uint32_t a;
    asm("{ .reg .u64 t; cvta.to.shared.u64 t, %1; cvt.u32.u64 %0, t; }" : "=r"(a) : "l"(p));
    return a;
}

static __device__ __forceinline__ uint32_t pack_bf16(float lo, float hi) {
    __nv_bfloat162 h = __floats2bfloat162_rn(lo, hi);   // x=lo (low half), y=hi
    return *reinterpret_cast<uint32_t*>(&h);
}

#define LDSM4(r0, r1, r2, r3, addr)                                              \
    asm volatile("ldmatrix.sync.aligned.m8n8.x4.shared.b16 {%0,%1,%2,%3}, [%4];" \
                 : "=r"(r0), "=r"(r1), "=r"(r2), "=r"(r3) : "r"(addr))

static __device__ __forceinline__ void mma16816(float c[4],
        uint32_t a0, uint32_t a1, uint32_t a2, uint32_t a3,
        uint32_t b0, uint32_t b1) {
    asm volatile(
        "mma.sync.aligned.m16n8k16.row.col.f32.bf16.bf16.f32 "
        "{%0,%1,%2,%3}, {%4,%5,%6,%7}, {%8,%9}, {%0,%1,%2,%3};"
        : "+f"(c[0]), "+f"(c[1]), "+f"(c[2]), "+f"(c[3])
        : "r"(a0), "r"(a1), "r"(a2), "r"(a3), "r"(b0), "r"(b1));
}

static __device__ __forceinline__ void sts128(uint32_t addr, uint32_t a, uint32_t b,
                                              uint32_t c, uint32_t d) {
    asm volatile("st.shared.v4.b32 [%0], {%1,%2,%3,%4};"
                 :: "r"(addr), "r"(a), "r"(b), "r"(c), "r"(d) : "memory");
}
static __device__ __forceinline__ void sts32(uint32_t addr, uint32_t v) {
    asm volatile("st.shared.b32 [%0], %1;" :: "r"(addr), "r"(v) : "memory");
}

// One 128x128x128 GEMM: A = src H tile (bf16, swizzled), B in registers,
// epilogue relu(D + be[col]) written as bf16 to dst H tile.
static __device__ __forceinline__ void do_gemm(
    const uint32_t (&B)[4][8][2], uint32_t srcb, uint32_t dstb,
    const float* fA, int beoff, int w, int lane,
    uint32_t lrowoff, uint32_t r_lo, uint32_t khalf)
{
    const uint32_t erow  = lane >> 2;          // row within m-tile
    const uint32_t ecolq = lane & 3;           // col-pair index within n-tile
    const uint32_t rx    = erow & 7;           // swizzle xor for epilogue rows

    #pragma unroll 1
    for (int mt = 0; mt < 8; mt++) {
        float c[4][4];
        #pragma unroll
        for (int nt = 0; nt < 4; nt++)
            #pragma unroll
            for (int q = 0; q < 4; q++) c[nt][q] = 0.f;

        const uint32_t abase = srcb + (uint32_t)mt * 4096 + lrowoff;
        #pragma unroll
        for (int kc = 0; kc < 8; kc++) {
            uint32_t a0, a1, a2, a3;
            uint32_t aaddr = abase + ((((uint32_t)(kc * 2) + khalf) ^ r_lo) << 4);
            LDSM4(a0, a1, a2, a3, aaddr);
            #pragma unroll
            for (int nt = 0; nt < 4; nt++)
                mma16816(c[nt], a0, a1, a2, a3, B[nt][kc][0], B[nt][kc][1]);
        }

        const uint32_t row0 = (uint32_t)mt * 16 + erow;
        const uint32_t dst0 = dstb + row0 * 256;
        #pragma unroll
        for (int nt = 0; nt < 4; nt++) {
            int col = w * 32 + nt * 8 + (int)ecolq * 2;
            float bea = fA[beoff + col];
            float beb = fA[beoff + col + 1];
            float v0 = fmaxf(c[nt][0] + bea, 0.f);
            float v1 = fmaxf(c[nt][1] + beb, 0.f);
            float v2 = fmaxf(c[nt][2] + bea, 0.f);
            float v3 = fmaxf(c[nt][3] + beb, 0.f);
            uint32_t chunk = (uint32_t)(w * 4 + nt);
            uint32_t a0addr = dst0 + ((chunk ^ rx) << 4) + ecolq * 4;
            sts32(a0addr,        pack_bf16(v0, v1));
            sts32(a0addr + 2048, pack_bf16(v2, v3));   // row0+8: same xor (rx)
        }
    }
}

__global__ void __launch_bounds__(NTHREADS, 2)
ddpm_kernel(const float* __restrict__ noise, const float* __restrict__ z,
            const float* __restrict__ W0, const float* __restrict__ b0,
            const float* __restrict__ W1, const float* __restrict__ b1,
            const float* __restrict__ W2, const float* __restrict__ b2,
            const float* __restrict__ W3, const float* __restrict__ b3,
            const float* __restrict__ E0, const float* __restrict__ E1,
            const float* __restrict__ E2, float* __restrict__ out)
{
    extern __shared__ char smem_raw[];
    const uint32_t sb = smem_u32(smem_raw);
    float* fA = (float*)(smem_raw + SM_F32);

    const int tid  = threadIdx.x;
    const int lane = tid & 31;
    const int w    = tid >> 5;
    const int sample = blockIdx.x * TILE_M + tid;
    const bool valid = sample < BTOT;

    // ---- prologue: small tensors into SMEM ----
    fA[F_W0A + tid] = W0[tid];          // W0[0][j]
    fA[F_W0B + tid] = W0[NU + tid];     // W0[1][j]
    if (tid < 2) fA[F_B3 + tid] = b3[tid];

    // schedule constants
    if (tid == 0) {
        double prod = 1.0;
        for (int t = 0; t < NSTEPS; t++) {
            double xl = -6.0 + 12.0 * (double)t / 99.0;
            double beta = (1.0 / (1.0 + exp(-xl))) * (0.005 - 1e-5) + 1e-5;
            double alpha = 1.0 - beta;
            prod *= alpha;
            fA[F_COEF + t]  = (float)(beta / sqrt(1.0 - prod));
            fA[F_INVAS + t] = (float)(1.0 / sqrt(alpha));
            fA[F_BSQ + t]   = (float)sqrt(beta);
        }
    }

    // ---- weight B-fragments in registers (per-warp N slice) ----
    // m16n8k16 B frag: lane holds B[k0..][n], n = w*32 + nt*8 + lane/4, k0 = kc*16+(lane%4)*2
    uint32_t B1[4][8][2], B2[4][8][2], B3f[8][2];
    {
        const int n0 = w * 32 + (lane >> 2);
        const int kb = (lane & 3) * 2;
        #pragma unroll
        for (int nt = 0; nt < 4; nt++) {
            int n = n0 + nt * 8;
            #pragma unroll
            for (int kc = 0; kc < 8; kc++) {
                int k0 = kc * 16 + kb;
                B1[nt][kc][0] = pack_bf16(W1[k0 * NU + n],       W1[(k0 + 1) * NU + n]);
                B1[nt][kc][1] = pack_bf16(W1[(k0 + 8) * NU + n], W1[(k0 + 9) * NU + n]);
                B2[nt][kc][0] = pack_bf16(W2[k0 * NU + n],       W2[(k0 + 1) * NU + n]);
                B2[nt][kc][1] = pack_bf16(W2[(k0 + 8) * NU + n], W2[(k0 + 9) * NU + n]);
            }
        }
        // W3 (128x2) padded to n=8
        const int n3 = lane >> 2;
        #pragma unroll
        for (int kc = 0; kc < 8; kc++) {
            int k0 = kc * 16 + kb;
            float v00 = (n3 < 2) ? W3[k0 * 2 + n3]       : 0.f;
            float v01 = (n3 < 2) ? W3[(k0 + 1) * 2 + n3] : 0.f;
            float v10 = (n3 < 2) ? W3[(k0 + 8) * 2 + n3] : 0.f;
            float v11 = (n3 < 2) ? W3[(k0 + 9) * 2 + n3] : 0.f;
            B3f[kc][0] = pack_bf16(v00, v01);
            B3f[kc][1] = pack_bf16(v10, v11);
        }
    }

    // ---- per-thread state ----
    float x0 = 0.f, x1 = 0.f;
    if (valid) {
        float2 n2 = ((const float2*)noise)[sample];
        x0 = n2.x; x1 = n2.y;
    }

    // per-lane ldmatrix constants
    const uint32_t r_lo   = (uint32_t)(lane & 7);
    const uint32_t half   = (uint32_t)((lane >> 3) & 1);
    const uint32_t khalf  = (uint32_t)(lane >> 4);
    const uint32_t lrowoff = (half * 8 + r_lo) * 256;

    const uint32_t sbHP = sb + SM_HP;
    const uint32_t sbHQ = sb + SM_HQ;
    const uint32_t myrow = sbHP + (uint32_t)tid * 256;
    const uint32_t myxor = (uint32_t)(tid & 7);

    #pragma unroll 1
    for (int i = 0; i < NSTEPS; i++) {
        const int t = NSTEPS - 1 - i;

        // prefetch z
        float zc0 = 0.f, zc1 = 0.f;
        if (valid) {
            float2 zz = ((const float2*)z)[(size_t)i * BTOT + sample];
            zc0 = zz.x; zc1 = zz.y;
        }

        // per-step fused bias+embedding
        fA[F_BE0 + tid] = b0[tid] + E0[t * NU + tid];
        fA[F_BE1 + tid] = b1[tid] + E1[t * NU + tid];
        fA[F_BE2 + tid] = b2[tid] + E2[t * NU + tid];
        __syncthreads();

        // ---- layer 0 (fp32 scalar): h1 = relu(x @ W0 + be0) -> HP ----
        #pragma unroll
        for (int j = 0; j < NU; j += 8) {
            float4 wa0 = *(const float4*)&fA[F_W0A + j];
            float4 wa1 = *(const float4*)&fA[F_W0A + j + 4];
            float4 wb0 = *(const float4*)&fA[F_W0B + j];
            float4 wb1 = *(const float4*)&fA[F_W0B + j + 4];
            float4 be0v = *(const float4*)&fA[F_BE0 + j];
            float4 be1v = *(const float4*)&fA[F_BE0 + j + 4];
            float v0 = fmaxf(fmaf(x0, wa0.x, fmaf(x1, wb0.x, be0v.x)), 0.f);
            float v1 = fmaxf(fmaf(x0, wa0.y, fmaf(x1, wb0.y, be0v.y)), 0.f);
            float v2 = fmaxf(fmaf(x0, wa0.z, fmaf(x1, wb0.z, be0v.z)), 0.f);
            float v3 = fmaxf(fmaf(x0, wa0.w, fmaf(x1, wb0.w, be0v.w)), 0.f);
            float v4 = fmaxf(fmaf(x0, wa1.x, fmaf(x1, wb1.x, be1v.x)), 0.f);
            float v5 = fmaxf(fmaf(x0, wa1.y, fmaf(x1, wb1.y, be1v.y)), 0.f);
            float v6 = fmaxf(fmaf(x0, wa1.z, fmaf(x1, wb1.z, be1v.z)), 0.f);
            float v7 = fmaxf(fmaf(x0, wa1.w, fmaf(x1, wb1.w, be1v.w)), 0.f);
            uint32_t addr = myrow + ((((uint32_t)(j >> 3)) ^ myxor) << 4);
            sts128(addr, pack_bf16(v0, v1), pack_bf16(v2, v3),
                         pack_bf16(v4, v5), pack_bf16(v6, v7));
        }
        __syncthreads();

        // ---- GEMM1: HQ = relu(HP @ W1 + be1) ----
        do_gemm(B1, sbHP, sbHQ, fA, F_BE1, w, lane, lrowoff, r_lo, khalf);
        __syncthreads();

        // ---- GEMM2: HP = relu(HQ @ W2 + be2)  (h3) ----
        do_gemm(B2, sbHQ, sbHP, fA, F_BE2, w, lane, lrowoff, r_lo, khalf);
        __syncthreads();

        // ---- GEMM3: pred = h3 @ W3 (n padded to 8); warp w covers rows [32w, 32w+32) ----
        {
            float c3[2][4];
            #pragma unroll
            for (int ml = 0; ml < 2; ml++)
                #pragma unroll
                for (int q = 0; q < 4; q++) c3[ml][q] = 0.f;

            #pragma unroll
            for (int ml = 0; ml < 2; ml++) {
                uint32_t abase = sbHP + (uint32_t)(w * 2 + ml) * 4096 + lrowoff;
                #pragma unroll
                for (int kc = 0; kc < 8; kc++) {
                    uint32_t a0, a1, a2, a3;
                    uint32_t aaddr = abase + ((((uint32_t)(kc * 2) + khalf) ^ r_lo) << 4);
                    LDSM4(a0, a1, a2, a3, aaddr);
                    mma16816(c3[ml], a0, a1, a2, a3, B3f[kc][0], B3f[kc][1]);
                }
            }
            // lanes with (lane&3)==0 hold cols 0,1 for rows g and g+8 of each m-tile
            if ((lane & 3) == 0) {
                int g = lane >> 2;
                int r0 = w * 32 + g;
                fA[F_PRED + 2 * r0]            = c3[0][0];
                fA[F_PRED + 2 * r0 + 1]        = c3[0][1];
                fA[F_PRED + 2 * (r0 + 8)]      = c3[0][2];
                fA[F_PRED + 2 * (r0 + 8) + 1]  = c3[0][3];
                int r1 = w * 32 + 16 + g;
                fA[F_PRED + 2 * r1]            = c3[1][0];
                fA[F_PRED + 2 * r1 + 1]        = c3[1][1];
                fA[F_PRED + 2 * (r1 + 8)]      = c3[1][2];
                fA[F_PRED + 2 * (r1 + 8) + 1]  = c3[1][3];
            }
        }
        __syncthreads();

        // ---- x update ----
        {
            float p0 = fA[F_PRED + 2 * tid]     + fA[F_B3 + 0];
            float p1 = fA[F_PRED + 2 * tid + 1] + fA[F_B3 + 1];
            float cf = fA[F_COEF + t], ia = fA[F_INVAS + t], bq = fA[F_BSQ + t];
            x0 = (x0 - cf * p0) * ia + bq * zc0;
            x1 = (x1 - cf * p1) * ia + bq * zc1;
        }
        __syncthreads();   // F_PRED / H buffers reused next step
    }

    if (valid) {
        ((float2*)out)[sample] = make_float2(x0, x1);
    }
}

extern "C" void kernel_launch(void* const* d_in, const int* in_sizes, int n_in,
                              void* d_out, int out_size) {
    (void)in_sizes; (void)n_in; (void)out_size;
    const float* noise = (const float*)d_in[0];
    const float* z     = (const float*)d_in[1];
    const float* W0    = (const float*)d_in[2];
    const float* b0    = (const float*)d_in[3];
    const float* W1    = (const float*)d_in[4];
    const float* b1    = (const float*)d_in[5];
    const float* W2    = (const float*)d_in[6];
    const float* b2    = (const float*)d_in[7];
    const float* W3    = (const float*)d_in[8];
    const float* b3    = (const float*)d_in[9];
    const float* E0    = (const float*)d_in[10];
    const float* E1    = (const float*)d_in[11];
    const float* E2    = (const float*)d_in[12];
    float* out = (float*)d_out;

    cudaFuncSetAttribute(ddpm_kernel, cudaFuncAttributeMaxDynamicSharedMemorySize, SMEM_TOTAL);

    dim3 grid((BTOT + TILE_M - 1) / TILE_M);
    ddpm_kernel<<<grid, NTHREADS, SMEM_TOTAL>>>(noise, z, W0, b0, W1, b1, W2, b2,
                                                W3, b3, E0, E1, E2, out);
}